// round 3
// baseline (speedup 1.0000x reference)
#include <cuda_runtime.h>
#include <cuda_bf16.h>
#include <math.h>

// Problem constants
#define BATCH 512
#define FDIM  512
#define CLS   100000

#define S_SCALE 32.0f
#define T_BOOST 1.1f
#define ALPHA_B 0.25f
#define M0_C    0.4f
#define M1_C    0.2f

// GEMM tiling
#define BM 128
#define BN 128
#define BK 8
#define TM 8
#define TN 8
#define NTHREADS 256

// ---------------------------------------------------------------------------
// Device-global scratch (no allocations allowed)
// ---------------------------------------------------------------------------
__device__ float g_xn[BATCH * FDIM];     // normalized x
__device__ float g_gt[BATCH];            // gt cosine per row
__device__ float g_thresh[BATCH];        // cos(acos(gt)+m0)
__device__ int   g_label[BATCH];
__device__ float g_sumexp[BATCH];        // sum exp(S*cos') over c != label
__device__ float g_sumboost[BATCH];      // sum boosted values over mask
__device__ float g_cnt[BATCH];           // count of hard negatives
__device__ int   g_is64;                 // label dtype flag

// ---------------------------------------------------------------------------
// Kernel 0: detect label dtype (int32 vs int64).
// Reads only the first 512 int32 words — safe under both layouts.
// int64 layout: words at odd indices are high halves of values < 2^31 -> all 0.
// ---------------------------------------------------------------------------
__global__ void detect_kernel(const int* __restrict__ label_raw)
{
    if (threadIdx.x == 0 && blockIdx.x == 0) {
        int is64 = 1;
        for (int i = 1; i < 2 * BATCH && i < 512; i += 2) {
            if (label_raw[i] != 0) { is64 = 0; break; }
        }
        g_is64 = is64;
    }
}

// ---------------------------------------------------------------------------
// Kernel A: per-row prep. One block per batch row.
// ---------------------------------------------------------------------------
__global__ __launch_bounds__(256) void prep_kernel(
    const float* __restrict__ x,
    const void* __restrict__ label,
    const float* __restrict__ W)
{
    const int b = blockIdx.x;
    const int t = threadIdx.x;

    __shared__ float xs[FDIM];
    __shared__ float s3[8][3];     // per-warp partials: xss, wss, dot
    __shared__ float s_bcast;      // invx broadcast
    __shared__ int   sL;

    if (t == 0) {
        int L;
        if (g_is64) L = (int)((const long long*)label)[b];
        else        L = ((const int*)label)[b];
        // sanitize (defensive: keep all accesses in-bounds no matter what)
        if (L < 0 || L >= CLS) L = 0;
        sL = L;
    }
    __syncthreads();
    const int L = sL;

    float xss = 0.f;
    for (int i = t; i < FDIM; i += 256) {
        float v = x[b * FDIM + i];
        xs[i] = v;
        xss += v * v;
    }
    __syncthreads();

    float wss = 0.f, dt = 0.f;
    const float* wrow = W + (size_t)L * FDIM;
    for (int i = t; i < FDIM; i += 256) {
        float w = wrow[i];
        wss += w * w;
        dt  += w * xs[i];
    }

    #pragma unroll
    for (int off = 16; off >= 1; off >>= 1) {
        xss += __shfl_down_sync(0xffffffffu, xss, off);
        wss += __shfl_down_sync(0xffffffffu, wss, off);
        dt  += __shfl_down_sync(0xffffffffu, dt,  off);
    }
    const int warp = t >> 5;
    if ((t & 31) == 0) { s3[warp][0] = xss; s3[warp][1] = wss; s3[warp][2] = dt; }
    __syncthreads();

    if (t == 0) {
        float X = 0.f, Wn = 0.f, D = 0.f;
        #pragma unroll
        for (int w = 0; w < 8; w++) { X += s3[w][0]; Wn += s3[w][1]; D += s3[w][2]; }
        float nx = fmaxf(sqrtf(X), 1e-12f);
        float nw = fmaxf(sqrtf(Wn), 1e-12f);
        float invx = 1.0f / nx;
        s_bcast = invx;
        float gt = D * invx / nw;
        gt = fminf(fmaxf(gt, -1.0f), 1.0f);
        g_gt[b] = gt;
        g_thresh[b] = cosf(acosf(gt) + M0_C);
        g_label[b] = L;
        g_sumexp[b] = 0.f;
        g_sumboost[b] = 0.f;
        g_cnt[b] = 0.f;
    }
    __syncthreads();

    const float invx = s_bcast;
    for (int i = t; i < FDIM; i += 256) {
        g_xn[b * FDIM + i] = xs[i] * invx;
    }
}

// ---------------------------------------------------------------------------
// Kernel B: main fused GEMM + epilogue.
// ---------------------------------------------------------------------------
__global__ __launch_bounds__(NTHREADS) void gemm_epilogue_kernel(
    const float* __restrict__ W)
{
    __shared__ float sA[BK][BM];
    __shared__ float sB[BK][BN];
    __shared__ float sWss[BN];
    __shared__ float sInv[BN];

    const int tid = threadIdx.x;
    const int tx = tid & 15;       // class groups of 8
    const int ty = tid >> 4;       // batch groups of 8
    const int m0 = blockIdx.y * BM;
    const int n0 = blockIdx.x * BN;

    const int ldRow  = tid >> 1;          // 0..127
    const int ldCol4 = (tid & 1) * 4;     // 0 or 4

    const float* Aptr = g_xn + (size_t)(m0 + ldRow) * FDIM + ldCol4;
    const int cls = n0 + ldRow;
    const bool clsOK = (cls < CLS);
    const float* Bptr = W + (size_t)(clsOK ? cls : 0) * FDIM + ldCol4;

    float acc[TM][TN];
    #pragma unroll
    for (int i = 0; i < TM; i++)
        #pragma unroll
        for (int j = 0; j < TN; j++) acc[i][j] = 0.f;

    float wss = 0.f;

    for (int k0 = 0; k0 < FDIM; k0 += BK) {
        float4 a4 = *(const float4*)(Aptr + k0);
        float4 b4;
        if (clsOK) b4 = *(const float4*)(Bptr + k0);
        else       b4 = make_float4(0.f, 0.f, 0.f, 0.f);

        sA[ldCol4 + 0][ldRow] = a4.x;
        sA[ldCol4 + 1][ldRow] = a4.y;
        sA[ldCol4 + 2][ldRow] = a4.z;
        sA[ldCol4 + 3][ldRow] = a4.w;
        sB[ldCol4 + 0][ldRow] = b4.x;
        sB[ldCol4 + 1][ldRow] = b4.y;
        sB[ldCol4 + 2][ldRow] = b4.z;
        sB[ldCol4 + 3][ldRow] = b4.w;
        wss = fmaf(b4.x, b4.x, wss);
        wss = fmaf(b4.y, b4.y, wss);
        wss = fmaf(b4.z, b4.z, wss);
        wss = fmaf(b4.w, b4.w, wss);
        __syncthreads();

        #pragma unroll
        for (int k = 0; k < BK; k++) {
            float4 a0 = *(const float4*)&sA[k][ty * TM];
            float4 a1 = *(const float4*)&sA[k][ty * TM + 4];
            float4 b0 = *(const float4*)&sB[k][tx * TN];
            float4 b1 = *(const float4*)&sB[k][tx * TN + 4];
            float ra[TM] = {a0.x, a0.y, a0.z, a0.w, a1.x, a1.y, a1.z, a1.w};
            float rb[TN] = {b0.x, b0.y, b0.z, b0.w, b1.x, b1.y, b1.z, b1.w};
            #pragma unroll
            for (int i = 0; i < TM; i++)
                #pragma unroll
                for (int j = 0; j < TN; j++)
                    acc[i][j] = fmaf(ra[i], rb[j], acc[i][j]);
        }
        __syncthreads();
    }

    // reduce the two per-class sumsq halves
    if ((tid & 1) == 0) sWss[ldRow] = wss;
    __syncthreads();
    if ((tid & 1) == 1) sWss[ldRow] += wss;
    __syncthreads();
    if (tid < BN) {
        float nw = fmaxf(sqrtf(sWss[tid]), 1e-12f);
        sInv[tid] = 1.0f / nw;
    }
    __syncthreads();

    // epilogue
    int   lab[TM];
    float th[TM];
    #pragma unroll
    for (int i = 0; i < TM; i++) {
        int gm = m0 + ty * TM + i;
        lab[i] = g_label[gm];
        th[i]  = g_thresh[gm];
    }

    float rSum[TM], rBoost[TM], rCnt[TM];
    #pragma unroll
    for (int i = 0; i < TM; i++) { rSum[i] = 0.f; rBoost[i] = 0.f; rCnt[i] = 0.f; }

    #pragma unroll
    for (int j = 0; j < TN; j++) {
        const int c = n0 + tx * TN + j;
        const bool cok = (c < CLS);
        const float inv = sInv[tx * TN + j];
        #pragma unroll
        for (int i = 0; i < TM; i++) {
            if (cok && c != lab[i]) {
                float cv = acc[i][j] * inv;
                cv = fminf(fmaxf(cv, -1.0f), 1.0f);
                bool hard = (cv > th[i]);
                float v = hard ? fmaf(T_BOOST, cv, ALPHA_B) : cv;
                rSum[i] += __expf(S_SCALE * v);
                if (hard) { rBoost[i] += v; rCnt[i] += 1.0f; }
            }
        }
    }

    #pragma unroll
    for (int off = 8; off >= 1; off >>= 1) {
        #pragma unroll
        for (int i = 0; i < TM; i++) {
            rSum[i]   += __shfl_down_sync(0xffffffffu, rSum[i],   off, 16);
            rBoost[i] += __shfl_down_sync(0xffffffffu, rBoost[i], off, 16);
            rCnt[i]   += __shfl_down_sync(0xffffffffu, rCnt[i],   off, 16);
        }
    }
    if (tx == 0) {
        #pragma unroll
        for (int i = 0; i < TM; i++) {
            int gm = m0 + ty * TM + i;
            atomicAdd(&g_sumexp[gm],   rSum[i]);
            atomicAdd(&g_sumboost[gm], rBoost[i]);
            atomicAdd(&g_cnt[gm],      rCnt[i]);
        }
    }
}

// ---------------------------------------------------------------------------
// Kernel C: finalize. 1 block, 512 threads (one per batch row).
// ---------------------------------------------------------------------------
__global__ __launch_bounds__(512) void finalize_kernel(float* __restrict__ out)
{
    const int b = threadIdx.x;
    __shared__ double red[BATCH];

    float gt  = g_gt[b];
    float cnt = g_cnt[b];
    float sb  = g_sumboost[b];

    float lam = sb / fmaxf(cnt, 1.0f);
    float mi  = M0_C + ((cnt > 0.f) ? lam * M1_C : 0.f);
    float cosm = cosf(acosf(gt) + mi);
    float fg = (gt > 0.f) ? cosm : gt;

    double total = (double)g_sumexp[b] + exp((double)(S_SCALE * fg));
    double logp = log(total) - (double)(S_SCALE * fg);
    red[b] = logp;
    __syncthreads();

    #pragma unroll
    for (int s = 256; s > 0; s >>= 1) {
        if (b < s) red[b] += red[b + s];
        __syncthreads();
    }
    if (b == 0) {
        double L = red[0] / (double)BATCH;
        double p = exp(-L);
        double omp = 1.0 - p;
        out[0] = (float)(omp * omp * L);
    }
}

// ---------------------------------------------------------------------------
// Launch
// ---------------------------------------------------------------------------
extern "C" void kernel_launch(void* const* d_in, const int* in_sizes, int n_in,
                              void* d_out, int out_size)
{
    // Robust input identification by element count
    const float* x = nullptr; const void* label = nullptr; const float* W = nullptr;
    for (int i = 0; i < n_in; i++) {
        if (in_sizes[i] == BATCH * FDIM)      x = (const float*)d_in[i];
        else if (in_sizes[i] == BATCH)        label = d_in[i];
        else                                  W = (const float*)d_in[i];
    }
    float* out = (float*)d_out;
    (void)out_size;

    detect_kernel<<<1, 32>>>((const int*)label);
    prep_kernel<<<BATCH, 256>>>(x, label, W);

    dim3 grid((CLS + BN - 1) / BN, BATCH / BM);   // (782, 4)
    gemm_epilogue_kernel<<<grid, NTHREADS>>>(W);

    finalize_kernel<<<1, BATCH>>>(out);
}

// round 7
// speedup vs baseline: 2.6712x; 2.6712x over previous
#include <cuda_runtime.h>
#include <cuda_bf16.h>
#include <math.h>
#include <stdint.h>

// ---------------------------------------------------------------------------
// Problem constants
// ---------------------------------------------------------------------------
#define BATCH 512
#define FDIM  512
#define CLS   100000

#define S_SCALE 32.0f
#define T_BOOST 1.1f
#define ALPHA_B 0.25f
#define M0_C    0.4f
#define M1_C    0.2f

#define NTILES ((CLS + 127) / 128)   // 782 class tiles

// SMEM row stride (bf16 elements): 64 + 8 pad -> conflict-free quad access
#define SSTR 72

// ---------------------------------------------------------------------------
// Device-global scratch
// ---------------------------------------------------------------------------
__device__ __nv_bfloat16 g_xnbf[BATCH * FDIM];  // normalized x, bf16
__device__ float g_gt[BATCH];
__device__ float g_thresh[BATCH];
__device__ int   g_label[BATCH];
__device__ float g_sumexp[BATCH];
__device__ float g_sumboost[BATCH];
__device__ float g_cnt[BATCH];
__device__ int   g_is64;

// ---------------------------------------------------------------------------
// Kernel 0: detect label dtype (int32 vs int64)
// ---------------------------------------------------------------------------
__global__ void detect_kernel(const int* __restrict__ label_raw)
{
    if (threadIdx.x == 0 && blockIdx.x == 0) {
        int is64 = 1;
        for (int i = 1; i < 2 * BATCH && i < 512; i += 2) {
            if (label_raw[i] != 0) { is64 = 0; break; }
        }
        g_is64 = is64;
    }
}

// ---------------------------------------------------------------------------
// Kernel A: per-row prep (fp32 exact gt/thresh; bf16 xn for the GEMM)
// ---------------------------------------------------------------------------
__global__ __launch_bounds__(256) void prep_kernel(
    const float* __restrict__ x,
    const void* __restrict__ label,
    const float* __restrict__ W)
{
    const int b = blockIdx.x;
    const int t = threadIdx.x;

    __shared__ float xs[FDIM];
    __shared__ float s3[8][3];
    __shared__ float s_bcast;
    __shared__ int   sL;

    if (t == 0) {
        int L;
        if (g_is64) L = (int)((const long long*)label)[b];
        else        L = ((const int*)label)[b];
        if (L < 0 || L >= CLS) L = 0;
        sL = L;
    }
    __syncthreads();
    const int L = sL;

    float xss = 0.f;
    for (int i = t; i < FDIM; i += 256) {
        float v = x[b * FDIM + i];
        xs[i] = v;
        xss += v * v;
    }
    __syncthreads();

    float wss = 0.f, dt = 0.f;
    const float* wrow = W + (size_t)L * FDIM;
    for (int i = t; i < FDIM; i += 256) {
        float w = wrow[i];
        wss += w * w;
        dt  += w * xs[i];
    }

    #pragma unroll
    for (int off = 16; off >= 1; off >>= 1) {
        xss += __shfl_down_sync(0xffffffffu, xss, off);
        wss += __shfl_down_sync(0xffffffffu, wss, off);
        dt  += __shfl_down_sync(0xffffffffu, dt,  off);
    }
    const int warp = t >> 5;
    if ((t & 31) == 0) { s3[warp][0] = xss; s3[warp][1] = wss; s3[warp][2] = dt; }
    __syncthreads();

    if (t == 0) {
        float X = 0.f, Wn = 0.f, D = 0.f;
        #pragma unroll
        for (int w = 0; w < 8; w++) { X += s3[w][0]; Wn += s3[w][1]; D += s3[w][2]; }
        float nx = fmaxf(sqrtf(X), 1e-12f);
        float nw = fmaxf(sqrtf(Wn), 1e-12f);
        float invx = 1.0f / nx;
        s_bcast = invx;
        float gt = D * invx / nw;
        gt = fminf(fmaxf(gt, -1.0f), 1.0f);
        g_gt[b] = gt;
        g_thresh[b] = cosf(acosf(gt) + M0_C);
        g_label[b] = L;
        g_sumexp[b] = 0.f;
        g_sumboost[b] = 0.f;
        g_cnt[b] = 0.f;
    }
    __syncthreads();

    const float invx = s_bcast;
    for (int i = t; i < FDIM; i += 256) {
        g_xnbf[b * FDIM + i] = __float2bfloat16(xs[i] * invx);
    }
}

// ---------------------------------------------------------------------------
// mma.sync m16n8k16 bf16 wrapper (sm_80+, no 'a' feature needed)
// ---------------------------------------------------------------------------
__device__ __forceinline__ void mma16816(
    float* c, const uint32_t* a, const uint32_t* b)
{
    asm volatile(
        "mma.sync.aligned.m16n8k16.row.col.f32.bf16.bf16.f32 "
        "{%0,%1,%2,%3}, {%4,%5,%6,%7}, {%8,%9}, {%0,%1,%2,%3};"
        : "+f"(c[0]), "+f"(c[1]), "+f"(c[2]), "+f"(c[3])
        : "r"(a[0]), "r"(a[1]), "r"(a[2]), "r"(a[3]),
          "r"(b[0]), "r"(b[1]));
}

// ---------------------------------------------------------------------------
// Kernel B: warp-MMA bf16 GEMM + fused epilogue.
// Block tile 128(batch) x 128(classes), K=512 in 8 chunks of 64.
// 8 warps: 2(M) x 4(N), warp tile 64x32 (4x4 fragments of 16x8).
// ---------------------------------------------------------------------------
__global__ __launch_bounds__(256, 2) void gemm_mma_kernel(
    const float* __restrict__ W)
{
    __shared__ __align__(16) __nv_bfloat16 sA[128 * SSTR];
    __shared__ __align__(16) __nv_bfloat16 sB[128 * SSTR];
    __shared__ float sInv[128];
    __shared__ float sRed[3 * 128];   // sumexp / boost / cnt per local row

    const int tid  = threadIdx.x;
    const int wid  = tid >> 5;
    const int lane = tid & 31;
    const int g    = lane >> 2;      // 0..7
    const int t4   = lane & 3;       // 0..3
    const int warpM = wid & 1;       // 0..1 -> 64-row band
    const int warpN = wid >> 1;      // 0..3 -> 32-col band

    const int m0 = blockIdx.y * 128;
    const int n0 = blockIdx.x * 128;

    // loader mapping: thread -> (row 0..127, half 0/1 of 64-col chunk)
    const int br_r = tid >> 1;
    const int br_h = tid & 1;
    const int bcls = n0 + br_r;
    const bool bok = (bcls < CLS);
    const float* bsrc = W + (size_t)(bok ? bcls : 0) * FDIM + br_h * 32;
    const __nv_bfloat16* asrc = g_xnbf + (size_t)(m0 + br_r) * FDIM + br_h * 32;

    float acc[4][4][4];
    #pragma unroll
    for (int mi = 0; mi < 4; mi++)
        #pragma unroll
        for (int ni = 0; ni < 4; ni++)
            #pragma unroll
            for (int e = 0; e < 4; e++) acc[mi][ni][e] = 0.f;

    float wss = 0.f;

    for (int kc = 0; kc < 8; kc++) {
        // ---- load B: 128 classes x 64 cols fp32 -> bf16 (+ wss) ----
        {
            float4 f[8];
            if (bok) {
                const float4* src = (const float4*)(bsrc + kc * 64);
                #pragma unroll
                for (int i = 0; i < 8; i++) f[i] = src[i];
            } else {
                #pragma unroll
                for (int i = 0; i < 8; i++) f[i] = make_float4(0.f, 0.f, 0.f, 0.f);
            }
            #pragma unroll
            for (int i = 0; i < 8; i++) {
                wss = fmaf(f[i].x, f[i].x, wss);
                wss = fmaf(f[i].y, f[i].y, wss);
                wss = fmaf(f[i].z, f[i].z, wss);
                wss = fmaf(f[i].w, f[i].w, wss);
            }
            uint4* dst = (uint4*)(sB + br_r * SSTR + br_h * 32);
            #pragma unroll
            for (int i = 0; i < 4; i++) {
                __nv_bfloat162 p0 = __floats2bfloat162_rn(f[2*i].x,   f[2*i].y);
                __nv_bfloat162 p1 = __floats2bfloat162_rn(f[2*i].z,   f[2*i].w);
                __nv_bfloat162 p2 = __floats2bfloat162_rn(f[2*i+1].x, f[2*i+1].y);
                __nv_bfloat162 p3 = __floats2bfloat162_rn(f[2*i+1].z, f[2*i+1].w);
                uint4 v;
                v.x = *(uint32_t*)&p0; v.y = *(uint32_t*)&p1;
                v.z = *(uint32_t*)&p2; v.w = *(uint32_t*)&p3;
                dst[i] = v;
            }
        }
        // ---- load A: 128 rows x 64 cols bf16 ----
        {
            const uint4* src = (const uint4*)(asrc + kc * 64);
            uint4* dst = (uint4*)(sA + br_r * SSTR + br_h * 32);
            #pragma unroll
            for (int i = 0; i < 4; i++) dst[i] = src[i];
        }
        __syncthreads();

        // ---- compute: 4 k16-steps ----
        #pragma unroll
        for (int k16 = 0; k16 < 4; k16++) {
            uint32_t a[4][4];
            #pragma unroll
            for (int mi = 0; mi < 4; mi++) {
                const int r = warpM * 64 + mi * 16 + g;
                const uint32_t* p0 = (const uint32_t*)(sA + r * SSTR + k16 * 16);
                const uint32_t* p1 = (const uint32_t*)(sA + (r + 8) * SSTR + k16 * 16);
                a[mi][0] = p0[t4];
                a[mi][1] = p1[t4];
                a[mi][2] = p0[t4 + 4];
                a[mi][3] = p1[t4 + 4];
            }
            uint32_t b[4][2];
            #pragma unroll
            for (int ni = 0; ni < 4; ni++) {
                const int n = warpN * 32 + ni * 8 + g;
                const uint32_t* pb = (const uint32_t*)(sB + n * SSTR + k16 * 16);
                b[ni][0] = pb[t4];
                b[ni][1] = pb[t4 + 4];
            }
            #pragma unroll
            for (int mi = 0; mi < 4; mi++)
                #pragma unroll
                for (int ni = 0; ni < 4; ni++)
                    mma16816(acc[mi][ni], a[mi], b[ni]);
        }
        __syncthreads();
    }

    // ---- W-row norms -> sInv[128] (stage in sRed) ----
    if (br_h == 0) sRed[br_r] = wss;
    __syncthreads();
    if (br_h == 1) sRed[br_r] += wss;
    __syncthreads();
    if (tid < 128) {
        float nw = fmaxf(sqrtf(sRed[tid]), 1e-12f);
        sInv[tid] = 1.0f / nw;
    }
    __syncthreads();
    // zero reduction buffers
    for (int i = tid; i < 3 * 128; i += 256) sRed[i] = 0.f;
    __syncthreads();

    // ---- epilogue: mask/boost/exp, quad-reduce, shared atomics ----
    #pragma unroll
    for (int mi = 0; mi < 4; mi++) {
        const int rl0 = warpM * 64 + mi * 16 + g;   // local rows
        const int rl1 = rl0 + 8;
        const int r0 = m0 + rl0, r1 = m0 + rl1;
        const float th0 = g_thresh[r0], th1 = g_thresh[r1];
        const int  lab0 = g_label[r0],  lab1 = g_label[r1];

        float s0 = 0.f, bo0 = 0.f, cn0 = 0.f;
        float s1 = 0.f, bo1 = 0.f, cn1 = 0.f;

        #pragma unroll
        for (int ni = 0; ni < 4; ni++) {
            #pragma unroll
            for (int e = 0; e < 2; e++) {
                const int cl = warpN * 32 + ni * 8 + t4 * 2 + e;   // local col
                const int c  = n0 + cl;
                if (c < CLS) {
                    const float inv = sInv[cl];
                    // row g value
                    if (c != lab0) {
                        float cv = acc[mi][ni][e] * inv;
                        cv = fminf(fmaxf(cv, -1.0f), 1.0f);
                        bool hard = (cv > th0);
                        float v = hard ? fmaf(T_BOOST, cv, ALPHA_B) : cv;
                        s0 += __expf(S_SCALE * v);
                        if (hard) { bo0 += v; cn0 += 1.0f; }
                    }
                    // row g+8 value
                    if (c != lab1) {
                        float cv = acc[mi][ni][2 + e] * inv;
                        cv = fminf(fmaxf(cv, -1.0f), 1.0f);
                        bool hard = (cv > th1);
                        float v = hard ? fmaf(T_BOOST, cv, ALPHA_B) : cv;
                        s1 += __expf(S_SCALE * v);
                        if (hard) { bo1 += v; cn1 += 1.0f; }
                    }
                }
            }
        }

        // reduce across the quad (t4 = 0..3 share the same rows)
        #pragma unroll
        for (int off = 1; off <= 2; off <<= 1) {
            s0  += __shfl_down_sync(0xffffffffu, s0,  off, 4);
            bo0 += __shfl_down_sync(0xffffffffu, bo0, off, 4);
            cn0 += __shfl_down_sync(0xffffffffu, cn0, off, 4);
            s1  += __shfl_down_sync(0xffffffffu, s1,  off, 4);
            bo1 += __shfl_down_sync(0xffffffffu, bo1, off, 4);
            cn1 += __shfl_down_sync(0xffffffffu, cn1, off, 4);
        }
        if (t4 == 0) {
            atomicAdd(&sRed[rl0],       s0);
            atomicAdd(&sRed[128 + rl0], bo0);
            atomicAdd(&sRed[256 + rl0], cn0);
            atomicAdd(&sRed[rl1],       s1);
            atomicAdd(&sRed[128 + rl1], bo1);
            atomicAdd(&sRed[256 + rl1], cn1);
        }
    }
    __syncthreads();

    // ---- one global atomic per row per block ----
    if (tid < 128) {
        const int gm = m0 + tid;
        atomicAdd(&g_sumexp[gm],   sRed[tid]);
        atomicAdd(&g_sumboost[gm], sRed[128 + tid]);
        atomicAdd(&g_cnt[gm],      sRed[256 + tid]);
    }
}

// ---------------------------------------------------------------------------
// Kernel C: finalize
// ---------------------------------------------------------------------------
__global__ __launch_bounds__(512) void finalize_kernel(float* __restrict__ out)
{
    const int b = threadIdx.x;
    __shared__ double red[BATCH];

    float gt  = g_gt[b];
    float cnt = g_cnt[b];
    float sb  = g_sumboost[b];

    float lam = sb / fmaxf(cnt, 1.0f);
    float mi  = M0_C + ((cnt > 0.f) ? lam * M1_C : 0.f);
    float cosm = cosf(acosf(gt) + mi);
    float fg = (gt > 0.f) ? cosm : gt;

    double total = (double)g_sumexp[b] + exp((double)(S_SCALE * fg));
    double logp = log(total) - (double)(S_SCALE * fg);
    red[b] = logp;
    __syncthreads();

    #pragma unroll
    for (int s = 256; s > 0; s >>= 1) {
        if (b < s) red[b] += red[b + s];
        __syncthreads();
    }
    if (b == 0) {
        double L = red[0] / (double)BATCH;
        double p = exp(-L);
        double omp = 1.0 - p;
        out[0] = (float)(omp * omp * L);
    }
}

// ---------------------------------------------------------------------------
// Launch
// ---------------------------------------------------------------------------
extern "C" void kernel_launch(void* const* d_in, const int* in_sizes, int n_in,
                              void* d_out, int out_size)
{
    const float* x = nullptr; const void* label = nullptr; const float* W = nullptr;
    for (int i = 0; i < n_in; i++) {
        if (in_sizes[i] == BATCH * FDIM)      x = (const float*)d_in[i];
        else if (in_sizes[i] == BATCH)        label = d_in[i];
        else                                  W = (const float*)d_in[i];
    }
    float* out = (float*)d_out;
    (void)out_size;

    detect_kernel<<<1, 32>>>((const int*)label);
    prep_kernel<<<BATCH, 256>>>(x, label, W);

    dim3 grid(NTILES, BATCH / 128);   // (782, 4)
    gemm_mma_kernel<<<grid, 256>>>(W);

    finalize_kernel<<<1, BATCH>>>(out);
}

// round 8
// speedup vs baseline: 3.8959x; 1.4585x over previous
#include <cuda_runtime.h>
#include <cuda_bf16.h>
#include <math.h>
#include <stdint.h>

// ---------------------------------------------------------------------------
// Problem constants
// ---------------------------------------------------------------------------
#define BATCH 512
#define FDIM  512
#define CLS   100000

#define S_SCALE 32.0f
#define T_BOOST 1.1f
#define ALPHA_B 0.25f
#define M0_C    0.4f
#define M1_C    0.2f

#define NTILES ((CLS + 127) / 128)   // 782 class tiles

// SMEM row stride (bf16 elements): 64 + 8 pad -> conflict-free quad access
#define SSTR 72

// dynamic SMEM layout (bytes)
#define SMA_ST   (128 * SSTR * 2)            // 18432 per stage
#define SM_A0    0
#define SM_A1    SMA_ST
#define SM_B0    (2 * SMA_ST)
#define SM_B1    (3 * SMA_ST)
#define SM_RED   (4 * SMA_ST)                // 3*128 floats
#define SM_TOTAL (SM_RED + 3 * 128 * 4)      // 75264 B

// ---------------------------------------------------------------------------
// Device-global scratch
// ---------------------------------------------------------------------------
__device__ __nv_bfloat16 g_xnbf[BATCH * FDIM];            // normalized x, bf16
__device__ __nv_bfloat16 g_wnbf[(size_t)CLS * FDIM];      // normalized W, bf16 (102MB)
__device__ float g_gt[BATCH];
__device__ float g_thresh[BATCH];
__device__ int   g_label[BATCH];
__device__ float g_sumexp[BATCH];
__device__ float g_sumboost[BATCH];
__device__ float g_cnt[BATCH];
__device__ int   g_is64;

// ---------------------------------------------------------------------------
// PTX helpers
// ---------------------------------------------------------------------------
__device__ __forceinline__ uint32_t smem_u32_of(const void* p) {
    uint32_t a;
    asm("{ .reg .u64 t; cvta.to.shared.u64 t, %1; cvt.u32.u64 %0, t; }"
        : "=r"(a) : "l"(p));
    return a;
}

#define CP_ASYNC16(dst_u32, src_ptr) \
    asm volatile("cp.async.cg.shared.global [%0], [%1], 16;" \
        :: "r"(dst_u32), "l"(src_ptr) : "memory")
#define CP_COMMIT() \
    asm volatile("cp.async.commit_group;" ::: "memory")
#define CP_WAIT0() \
    asm volatile("cp.async.wait_group 0;" ::: "memory")

__device__ __forceinline__ void mma16816(
    float* c, const uint32_t* a, const uint32_t* b)
{
    asm volatile(
        "mma.sync.aligned.m16n8k16.row.col.f32.bf16.bf16.f32 "
        "{%0,%1,%2,%3}, {%4,%5,%6,%7}, {%8,%9}, {%0,%1,%2,%3};"
        : "+f"(c[0]), "+f"(c[1]), "+f"(c[2]), "+f"(c[3])
        : "r"(a[0]), "r"(a[1]), "r"(a[2]), "r"(a[3]),
          "r"(b[0]), "r"(b[1]));
}

// ---------------------------------------------------------------------------
// Kernel 0: detect label dtype (int32 vs int64)
// ---------------------------------------------------------------------------
__global__ void detect_kernel(const int* __restrict__ label_raw)
{
    if (threadIdx.x == 0 && blockIdx.x == 0) {
        int is64 = 1;
        for (int i = 1; i < 2 * BATCH && i < 512; i += 2) {
            if (label_raw[i] != 0) { is64 = 0; break; }
        }
        g_is64 = is64;
    }
}

// ---------------------------------------------------------------------------
// Kernel W: normalize W rows -> bf16 (one warp per class row)
// ---------------------------------------------------------------------------
__global__ __launch_bounds__(256) void wn_kernel(const float* __restrict__ W)
{
    const int row  = blockIdx.x * 8 + (threadIdx.x >> 5);
    const int lane = threadIdx.x & 31;
    if (row >= CLS) return;

    const float4* src = (const float4*)(W + (size_t)row * FDIM);
    float4 f[4];
    float ss = 0.f;
    #pragma unroll
    for (int i = 0; i < 4; i++) {
        f[i] = src[lane + 32 * i];
        ss = fmaf(f[i].x, f[i].x, ss);
        ss = fmaf(f[i].y, f[i].y, ss);
        ss = fmaf(f[i].z, f[i].z, ss);
        ss = fmaf(f[i].w, f[i].w, ss);
    }
    #pragma unroll
    for (int off = 16; off >= 1; off >>= 1)
        ss += __shfl_xor_sync(0xffffffffu, ss, off);

    const float inv = 1.0f / fmaxf(sqrtf(ss), 1e-12f);

    uint2* dst = (uint2*)(g_wnbf + (size_t)row * FDIM);
    #pragma unroll
    for (int i = 0; i < 4; i++) {
        __nv_bfloat162 p0 = __floats2bfloat162_rn(f[i].x * inv, f[i].y * inv);
        __nv_bfloat162 p1 = __floats2bfloat162_rn(f[i].z * inv, f[i].w * inv);
        uint2 v;
        v.x = *(uint32_t*)&p0;
        v.y = *(uint32_t*)&p1;
        dst[lane + 32 * i] = v;
    }
}

// ---------------------------------------------------------------------------
// Kernel A: per-row prep (fp32 exact gt/thresh; bf16 xn for the GEMM)
// ---------------------------------------------------------------------------
__global__ __launch_bounds__(256) void prep_kernel(
    const float* __restrict__ x,
    const void* __restrict__ label,
    const float* __restrict__ W)
{
    const int b = blockIdx.x;
    const int t = threadIdx.x;

    __shared__ float xs[FDIM];
    __shared__ float s3[8][3];
    __shared__ float s_bcast;
    __shared__ int   sL;

    if (t == 0) {
        int L;
        if (g_is64) L = (int)((const long long*)label)[b];
        else        L = ((const int*)label)[b];
        if (L < 0 || L >= CLS) L = 0;
        sL = L;
    }
    __syncthreads();
    const int L = sL;

    float xss = 0.f;
    for (int i = t; i < FDIM; i += 256) {
        float v = x[b * FDIM + i];
        xs[i] = v;
        xss += v * v;
    }
    __syncthreads();

    float wss = 0.f, dt = 0.f;
    const float* wrow = W + (size_t)L * FDIM;
    for (int i = t; i < FDIM; i += 256) {
        float w = wrow[i];
        wss += w * w;
        dt  += w * xs[i];
    }

    #pragma unroll
    for (int off = 16; off >= 1; off >>= 1) {
        xss += __shfl_down_sync(0xffffffffu, xss, off);
        wss += __shfl_down_sync(0xffffffffu, wss, off);
        dt  += __shfl_down_sync(0xffffffffu, dt,  off);
    }
    const int warp = t >> 5;
    if ((t & 31) == 0) { s3[warp][0] = xss; s3[warp][1] = wss; s3[warp][2] = dt; }
    __syncthreads();

    if (t == 0) {
        float X = 0.f, Wn = 0.f, D = 0.f;
        #pragma unroll
        for (int w = 0; w < 8; w++) { X += s3[w][0]; Wn += s3[w][1]; D += s3[w][2]; }
        float nx = fmaxf(sqrtf(X), 1e-12f);
        float nw = fmaxf(sqrtf(Wn), 1e-12f);
        float invx = 1.0f / nx;
        s_bcast = invx;
        float gt = D * invx / nw;
        gt = fminf(fmaxf(gt, -1.0f), 1.0f);
        g_gt[b] = gt;
        g_thresh[b] = cosf(acosf(gt) + M0_C);
        g_label[b] = L;
        g_sumexp[b] = 0.f;
        g_sumboost[b] = 0.f;
        g_cnt[b] = 0.f;
    }
    __syncthreads();

    const float invx = s_bcast;
    for (int i = t; i < FDIM; i += 256) {
        g_xnbf[b * FDIM + i] = __float2bfloat16(xs[i] * invx);
    }
}

// ---------------------------------------------------------------------------
// Kernel B: warp-MMA bf16 GEMM, cp.async double-buffered, fused epilogue.
// grid = (4 batch bands [fastest], 782 class tiles) so the 4 blocks sharing
// a Wn tile run consecutively -> Wn served once from DRAM, 3x from L2.
// ---------------------------------------------------------------------------
__global__ __launch_bounds__(256, 2) void gemm_mma_kernel()
{
    extern __shared__ char dsm[];
    __nv_bfloat16* sA[2] = { (__nv_bfloat16*)(dsm + SM_A0), (__nv_bfloat16*)(dsm + SM_A1) };
    __nv_bfloat16* sB[2] = { (__nv_bfloat16*)(dsm + SM_B0), (__nv_bfloat16*)(dsm + SM_B1) };
    float* sRed = (float*)(dsm + SM_RED);
    const uint32_t smem_base = smem_u32_of(dsm);

    const int tid  = threadIdx.x;
    const int wid  = tid >> 5;
    const int lane = tid & 31;
    const int g    = lane >> 2;
    const int t4   = lane & 3;
    const int warpM = wid & 1;
    const int warpN = wid >> 1;

    const int m0 = blockIdx.x * 128;   // batch band (4 bands, fastest dim)
    const int n0 = blockIdx.y * 128;   // class tile

    // loader mapping: thread -> (row 0..127, half 0/1 of 64-col chunk)
    const int br_r = tid >> 1;
    const int br_h = tid & 1;
    const int bcls = n0 + br_r;
    const bool bok = (bcls < CLS);
    const __nv_bfloat16* asrc = g_xnbf + (size_t)(m0 + br_r) * FDIM + br_h * 32;
    const __nv_bfloat16* bsrc = g_wnbf + (size_t)(bok ? bcls : 0) * FDIM + br_h * 32;
    const uint32_t adst = smem_base + (uint32_t)(br_r * SSTR + br_h * 32) * 2;
    const uint32_t bdst = adst + (uint32_t)SM_B0;

    float acc[4][4][4];
    #pragma unroll
    for (int mi = 0; mi < 4; mi++)
        #pragma unroll
        for (int ni = 0; ni < 4; ni++)
            #pragma unroll
            for (int e = 0; e < 4; e++) acc[mi][ni][e] = 0.f;

    // prefetch chunk 0
    {
        const __nv_bfloat16* ap = asrc;
        const __nv_bfloat16* bp = bsrc;
        #pragma unroll
        for (int i = 0; i < 4; i++) {
            CP_ASYNC16(adst + i * 16, ap + i * 8);
            CP_ASYNC16(bdst + i * 16, bp + i * 8);
        }
        CP_COMMIT();
    }

    for (int kc = 0; kc < 8; kc++) {
        const int s = kc & 1;

        CP_WAIT0();
        __syncthreads();          // stage s ready for all threads

        // prefetch next chunk into stage s^1 (its last readers finished
        // compute(kc-1) before the syncthreads above)
        if (kc + 1 < 8) {
            const uint32_t soff = (uint32_t)((kc + 1) & 1) * SMA_ST;
            const __nv_bfloat16* ap = asrc + (kc + 1) * 64;
            const __nv_bfloat16* bp = bsrc + (kc + 1) * 64;
            #pragma unroll
            for (int i = 0; i < 4; i++) {
                CP_ASYNC16(adst + soff + i * 16, ap + i * 8);
                CP_ASYNC16(bdst + soff + i * 16, bp + i * 8);
            }
            CP_COMMIT();
        }

        // ---- compute on stage s: 4 k16-steps ----
        const __nv_bfloat16* cA = sA[s];
        const __nv_bfloat16* cB = sB[s];
        #pragma unroll
        for (int k16 = 0; k16 < 4; k16++) {
            uint32_t a[4][4];
            #pragma unroll
            for (int mi = 0; mi < 4; mi++) {
                const int r = warpM * 64 + mi * 16 + g;
                const uint32_t* p0 = (const uint32_t*)(cA + r * SSTR + k16 * 16);
                const uint32_t* p1 = (const uint32_t*)(cA + (r + 8) * SSTR + k16 * 16);
                a[mi][0] = p0[t4];
                a[mi][1] = p1[t4];
                a[mi][2] = p0[t4 + 4];
                a[mi][3] = p1[t4 + 4];
            }
            uint32_t b[4][2];
            #pragma unroll
            for (int ni = 0; ni < 4; ni++) {
                const int n = warpN * 32 + ni * 8 + g;
                const uint32_t* pb = (const uint32_t*)(cB + n * SSTR + k16 * 16);
                b[ni][0] = pb[t4];
                b[ni][1] = pb[t4 + 4];
            }
            #pragma unroll
            for (int mi = 0; mi < 4; mi++)
                #pragma unroll
                for (int ni = 0; ni < 4; ni++)
                    mma16816(acc[mi][ni], a[mi], b[ni]);
        }
        __syncthreads();          // all readers done before stage s is refilled
    }

    // ---- zero reduction buffers ----
    for (int i = tid; i < 3 * 128; i += 256) sRed[i] = 0.f;
    __syncthreads();

    // ---- epilogue: mask/boost/exp, quad-reduce, shared atomics ----
    #pragma unroll
    for (int mi = 0; mi < 4; mi++) {
        const int rl0 = warpM * 64 + mi * 16 + g;
        const int rl1 = rl0 + 8;
        const int r0 = m0 + rl0, r1 = m0 + rl1;
        const float th0 = g_thresh[r0], th1 = g_thresh[r1];
        const int  lab0 = g_label[r0],  lab1 = g_label[r1];

        float s0 = 0.f, bo0 = 0.f, cn0 = 0.f;
        float s1 = 0.f, bo1 = 0.f, cn1 = 0.f;

        #pragma unroll
        for (int ni = 0; ni < 4; ni++) {
            #pragma unroll
            for (int e = 0; e < 2; e++) {
                const int cl = warpN * 32 + ni * 8 + t4 * 2 + e;
                const int c  = n0 + cl;
                if (c < CLS) {
                    if (c != lab0) {
                        float cv = acc[mi][ni][e];
                        cv = fminf(fmaxf(cv, -1.0f), 1.0f);
                        bool hard = (cv > th0);
                        float v = hard ? fmaf(T_BOOST, cv, ALPHA_B) : cv;
                        s0 += __expf(S_SCALE * v);
                        if (hard) { bo0 += v; cn0 += 1.0f; }
                    }
                    if (c != lab1) {
                        float cv = acc[mi][ni][2 + e];
                        cv = fminf(fmaxf(cv, -1.0f), 1.0f);
                        bool hard = (cv > th1);
                        float v = hard ? fmaf(T_BOOST, cv, ALPHA_B) : cv;
                        s1 += __expf(S_SCALE * v);
                        if (hard) { bo1 += v; cn1 += 1.0f; }
                    }
                }
            }
        }

        #pragma unroll
        for (int off = 1; off <= 2; off <<= 1) {
            s0  += __shfl_down_sync(0xffffffffu, s0,  off, 4);
            bo0 += __shfl_down_sync(0xffffffffu, bo0, off, 4);
            cn0 += __shfl_down_sync(0xffffffffu, cn0, off, 4);
            s1  += __shfl_down_sync(0xffffffffu, s1,  off, 4);
            bo1 += __shfl_down_sync(0xffffffffu, bo1, off, 4);
            cn1 += __shfl_down_sync(0xffffffffu, cn1, off, 4);
        }
        if (t4 == 0) {
            atomicAdd(&sRed[rl0],       s0);
            atomicAdd(&sRed[128 + rl0], bo0);
            atomicAdd(&sRed[256 + rl0], cn0);
            atomicAdd(&sRed[rl1],       s1);
            atomicAdd(&sRed[128 + rl1], bo1);
            atomicAdd(&sRed[256 + rl1], cn1);
        }
    }
    __syncthreads();

    if (tid < 128) {
        const int gm = m0 + tid;
        atomicAdd(&g_sumexp[gm],   sRed[tid]);
        atomicAdd(&g_sumboost[gm], sRed[128 + tid]);
        atomicAdd(&g_cnt[gm],      sRed[256 + tid]);
    }
}

// ---------------------------------------------------------------------------
// Kernel C: finalize
// ---------------------------------------------------------------------------
__global__ __launch_bounds__(512) void finalize_kernel(float* __restrict__ out)
{
    const int b = threadIdx.x;
    __shared__ double red[BATCH];

    float gt  = g_gt[b];
    float cnt = g_cnt[b];
    float sb  = g_sumboost[b];

    float lam = sb / fmaxf(cnt, 1.0f);
    float mi  = M0_C + ((cnt > 0.f) ? lam * M1_C : 0.f);
    float cosm = cosf(acosf(gt) + mi);
    float fg = (gt > 0.f) ? cosm : gt;

    double total = (double)g_sumexp[b] + exp((double)(S_SCALE * fg));
    double logp = log(total) - (double)(S_SCALE * fg);
    red[b] = logp;
    __syncthreads();

    #pragma unroll
    for (int s = 256; s > 0; s >>= 1) {
        if (b < s) red[b] += red[b + s];
        __syncthreads();
    }
    if (b == 0) {
        double L = red[0] / (double)BATCH;
        double p = exp(-L);
        double omp = 1.0 - p;
        out[0] = (float)(omp * omp * L);
    }
}

// ---------------------------------------------------------------------------
// Launch
// ---------------------------------------------------------------------------
extern "C" void kernel_launch(void* const* d_in, const int* in_sizes, int n_in,
                              void* d_out, int out_size)
{
    const float* x = nullptr; const void* label = nullptr; const float* W = nullptr;
    for (int i = 0; i < n_in; i++) {
        if (in_sizes[i] == BATCH * FDIM)      x = (const float*)d_in[i];
        else if (in_sizes[i] == BATCH)        label = d_in[i];
        else                                  W = (const float*)d_in[i];
    }
    float* out = (float*)d_out;
    (void)out_size;

    cudaFuncSetAttribute(gemm_mma_kernel,
                         cudaFuncAttributeMaxDynamicSharedMemorySize, SM_TOTAL);

    detect_kernel<<<1, 32>>>((const int*)label);
    wn_kernel<<<(CLS + 7) / 8, 256>>>(W);
    prep_kernel<<<BATCH, 256>>>(x, label, W);

    dim3 grid(BATCH / 128, NTILES);   // (4, 782) — band fastest for L2 reuse
    gemm_mma_kernel<<<grid, 256, SM_TOTAL>>>();

    finalize_kernel<<<1, BATCH>>>(out);
}

// round 9
// speedup vs baseline: 4.4240x; 1.1356x over previous
#include <cuda_runtime.h>
#include <cuda_bf16.h>
#include <math.h>
#include <stdint.h>

// ---------------------------------------------------------------------------
// Problem constants
// ---------------------------------------------------------------------------
#define BATCH 512
#define FDIM  512
#define CLS   100000

#define S_SCALE 32.0f
#define T_BOOST 1.1f
#define ALPHA_B 0.25f
#define M0_C    0.4f
#define M1_C    0.2f

#define NTILES ((CLS + 127) / 128)   // 782 class tiles

// SMEM row stride (bf16 elements): 64 + 8 pad
#define SSTR 72

// dynamic SMEM layout (bytes)
#define SMA_ST   (128 * SSTR * 2)            // 18432 per stage
#define SM_A0    0
#define SM_A1    SMA_ST
#define SM_B0    (2 * SMA_ST)
#define SM_B1    (3 * SMA_ST)
#define SM_RED   (4 * SMA_ST)                // 3*128 floats
#define SM_TOTAL (SM_RED + 3 * 128 * 4)      // 75264 B

// ---------------------------------------------------------------------------
// Device-global scratch
// ---------------------------------------------------------------------------
__device__ __nv_bfloat16 g_xnbf[BATCH * FDIM];            // normalized x, bf16
__device__ __nv_bfloat16 g_wnbf[(size_t)CLS * FDIM];      // normalized W, bf16
__device__ float g_gt[BATCH];
__device__ float g_thresh[BATCH];
__device__ int   g_label[BATCH];
__device__ float g_sumexp[BATCH];
__device__ float g_sumboost[BATCH];
__device__ float g_cnt[BATCH];
__device__ int   g_is64;

// ---------------------------------------------------------------------------
// PTX helpers
// ---------------------------------------------------------------------------
__device__ __forceinline__ uint32_t smem_u32_of(const void* p) {
    uint32_t a;
    asm("{ .reg .u64 t; cvta.to.shared.u64 t, %1; cvt.u32.u64 %0, t; }"
        : "=r"(a) : "l"(p));
    return a;
}

#define CP_ASYNC16(dst_u32, src_ptr) \
    asm volatile("cp.async.cg.shared.global [%0], [%1], 16;" \
        :: "r"(dst_u32), "l"(src_ptr) : "memory")
#define CP_COMMIT() \
    asm volatile("cp.async.commit_group;" ::: "memory")
#define CP_WAIT0() \
    asm volatile("cp.async.wait_group 0;" ::: "memory")

#define LDSM_X4(r0, r1, r2, r3, addr) \
    asm volatile("ldmatrix.sync.aligned.m8n8.x4.shared.b16 {%0,%1,%2,%3}, [%4];" \
        : "=r"(r0), "=r"(r1), "=r"(r2), "=r"(r3) : "r"(addr))

__device__ __forceinline__ void mma16816(
    float* c, const uint32_t* a, uint32_t b0, uint32_t b1)
{
    asm volatile(
        "mma.sync.aligned.m16n8k16.row.col.f32.bf16.bf16.f32 "
        "{%0,%1,%2,%3}, {%4,%5,%6,%7}, {%8,%9}, {%0,%1,%2,%3};"
        : "+f"(c[0]), "+f"(c[1]), "+f"(c[2]), "+f"(c[3])
        : "r"(a[0]), "r"(a[1]), "r"(a[2]), "r"(a[3]),
          "r"(b0), "r"(b1));
}

// ---------------------------------------------------------------------------
// Kernel 0: detect label dtype (int32 vs int64)
// ---------------------------------------------------------------------------
__global__ void detect_kernel(const int* __restrict__ label_raw)
{
    if (threadIdx.x == 0 && blockIdx.x == 0) {
        int is64 = 1;
        for (int i = 1; i < 2 * BATCH && i < 512; i += 2) {
            if (label_raw[i] != 0) { is64 = 0; break; }
        }
        g_is64 = is64;
    }
}

// ---------------------------------------------------------------------------
// Kernel W: normalize W rows -> bf16 (one warp per class row)
// ---------------------------------------------------------------------------
__global__ __launch_bounds__(256) void wn_kernel(const float* __restrict__ W)
{
    const int row  = blockIdx.x * 8 + (threadIdx.x >> 5);
    const int lane = threadIdx.x & 31;
    if (row >= CLS) return;

    const float4* src = (const float4*)(W + (size_t)row * FDIM);
    float4 f[4];
    float ss = 0.f;
    #pragma unroll
    for (int i = 0; i < 4; i++) {
        f[i] = src[lane + 32 * i];
        ss = fmaf(f[i].x, f[i].x, ss);
        ss = fmaf(f[i].y, f[i].y, ss);
        ss = fmaf(f[i].z, f[i].z, ss);
        ss = fmaf(f[i].w, f[i].w, ss);
    }
    #pragma unroll
    for (int off = 16; off >= 1; off >>= 1)
        ss += __shfl_xor_sync(0xffffffffu, ss, off);

    const float inv = 1.0f / fmaxf(sqrtf(ss), 1e-12f);

    uint2* dst = (uint2*)(g_wnbf + (size_t)row * FDIM);
    #pragma unroll
    for (int i = 0; i < 4; i++) {
        __nv_bfloat162 p0 = __floats2bfloat162_rn(f[i].x * inv, f[i].y * inv);
        __nv_bfloat162 p1 = __floats2bfloat162_rn(f[i].z * inv, f[i].w * inv);
        uint2 v;
        v.x = *(uint32_t*)&p0;
        v.y = *(uint32_t*)&p1;
        dst[lane + 32 * i] = v;
    }
}

// ---------------------------------------------------------------------------
// Kernel A: per-row prep (fp32 exact gt/thresh; bf16 xn for the GEMM)
// ---------------------------------------------------------------------------
__global__ __launch_bounds__(256) void prep_kernel(
    const float* __restrict__ x,
    const void* __restrict__ label,
    const float* __restrict__ W)
{
    const int b = blockIdx.x;
    const int t = threadIdx.x;

    __shared__ float xs[FDIM];
    __shared__ float s3[8][3];
    __shared__ float s_bcast;
    __shared__ int   sL;

    if (t == 0) {
        int L;
        if (g_is64) L = (int)((const long long*)label)[b];
        else        L = ((const int*)label)[b];
        if (L < 0 || L >= CLS) L = 0;
        sL = L;
    }
    __syncthreads();
    const int L = sL;

    float xss = 0.f;
    for (int i = t; i < FDIM; i += 256) {
        float v = x[b * FDIM + i];
        xs[i] = v;
        xss += v * v;
    }
    __syncthreads();

    float wss = 0.f, dt = 0.f;
    const float* wrow = W + (size_t)L * FDIM;
    for (int i = t; i < FDIM; i += 256) {
        float w = wrow[i];
        wss += w * w;
        dt  += w * xs[i];
    }

    #pragma unroll
    for (int off = 16; off >= 1; off >>= 1) {
        xss += __shfl_down_sync(0xffffffffu, xss, off);
        wss += __shfl_down_sync(0xffffffffu, wss, off);
        dt  += __shfl_down_sync(0xffffffffu, dt,  off);
    }
    const int warp = t >> 5;
    if ((t & 31) == 0) { s3[warp][0] = xss; s3[warp][1] = wss; s3[warp][2] = dt; }
    __syncthreads();

    if (t == 0) {
        float X = 0.f, Wn = 0.f, D = 0.f;
        #pragma unroll
        for (int w = 0; w < 8; w++) { X += s3[w][0]; Wn += s3[w][1]; D += s3[w][2]; }
        float nx = fmaxf(sqrtf(X), 1e-12f);
        float nw = fmaxf(sqrtf(Wn), 1e-12f);
        float invx = 1.0f / nx;
        s_bcast = invx;
        float gt = D * invx / nw;
        gt = fminf(fmaxf(gt, -1.0f), 1.0f);
        g_gt[b] = gt;
        g_thresh[b] = cosf(acosf(gt) + M0_C);
        g_label[b] = L;
        g_sumexp[b] = 0.f;
        g_sumboost[b] = 0.f;
        g_cnt[b] = 0.f;
    }
    __syncthreads();

    const float invx = s_bcast;
    for (int i = t; i < FDIM; i += 256) {
        g_xnbf[b * FDIM + i] = __float2bfloat16(xs[i] * invx);
    }
}

// ---------------------------------------------------------------------------
// Kernel B: warp-MMA bf16 GEMM, cp.async double-buffered, ldmatrix fragment
// loads, fused epilogue. grid = (4 batch bands fastest, 782 class tiles).
// ---------------------------------------------------------------------------
__global__ __launch_bounds__(256, 2) void gemm_mma_kernel()
{
    extern __shared__ char dsm[];
    float* sRed = (float*)(dsm + SM_RED);
    const uint32_t smem_base = smem_u32_of(dsm);

    const int tid  = threadIdx.x;
    const int wid  = tid >> 5;
    const int lane = tid & 31;
    const int g    = lane >> 2;
    const int t4   = lane & 3;
    const int warpM = wid & 1;
    const int warpN = wid >> 1;

    const int m0 = blockIdx.x * 128;   // batch band
    const int n0 = blockIdx.y * 128;   // class tile

    // loader mapping: thread -> (row 0..127, half 0/1 of 64-col chunk)
    const int br_r = tid >> 1;
    const int br_h = tid & 1;
    const int bcls = n0 + br_r;
    const bool bok = (bcls < CLS);
    const __nv_bfloat16* asrc = g_xnbf + (size_t)(m0 + br_r) * FDIM + br_h * 32;
    const __nv_bfloat16* bsrc = g_wnbf + (size_t)(bok ? bcls : 0) * FDIM + br_h * 32;
    const uint32_t adst = smem_base + (uint32_t)(br_r * SSTR + br_h * 32) * 2;
    const uint32_t bdst = adst + (uint32_t)SM_B0;

    // ldmatrix per-lane base addresses (stage 0, k16=0), bytes.
    // A fragments (16x16): groups of 8 lanes -> {rows 0-7 k0, rows 8-15 k0,
    //                                            rows 0-7 k8, rows 8-15 k8}
    uint32_t aoff[4];
    {
        const int arow = (lane & 7) + ((lane >> 3) & 1) * 8;
        const int akp  = (lane >> 4) * 8;
        #pragma unroll
        for (int mi = 0; mi < 4; mi++)
            aoff[mi] = smem_base +
                (uint32_t)(((warpM * 64 + mi * 16 + arow) * SSTR + akp) * 2);
    }
    // B fragment pairs (16 classes x 16 k): groups -> {n0-7 k0, n0-7 k8,
    //                                                  n8-15 k0, n8-15 k8}
    uint32_t boff[2];
    {
        const int brow = (lane & 7) + ((lane >> 4) & 1) * 8;
        const int bkp  = ((lane >> 3) & 1) * 8;
        #pragma unroll
        for (int p = 0; p < 2; p++)
            boff[p] = smem_base + (uint32_t)SM_B0 +
                (uint32_t)(((warpN * 32 + p * 16 + brow) * SSTR + bkp) * 2);
    }

    float acc[4][4][4];
    #pragma unroll
    for (int mi = 0; mi < 4; mi++)
        #pragma unroll
        for (int ni = 0; ni < 4; ni++)
            #pragma unroll
            for (int e = 0; e < 4; e++) acc[mi][ni][e] = 0.f;

    // prefetch chunk 0
    {
        #pragma unroll
        for (int i = 0; i < 4; i++) {
            CP_ASYNC16(adst + i * 16, asrc + i * 8);
            CP_ASYNC16(bdst + i * 16, bsrc + i * 8);
        }
        CP_COMMIT();
    }

    for (int kc = 0; kc < 8; kc++) {
        const uint32_t soff = (uint32_t)(kc & 1) * SMA_ST;

        CP_WAIT0();
        __syncthreads();          // stage ready for all threads

        if (kc + 1 < 8) {
            const uint32_t poff = (uint32_t)((kc + 1) & 1) * SMA_ST;
            const __nv_bfloat16* ap = asrc + (kc + 1) * 64;
            const __nv_bfloat16* bp = bsrc + (kc + 1) * 64;
            #pragma unroll
            for (int i = 0; i < 4; i++) {
                CP_ASYNC16(adst + poff + i * 16, ap + i * 8);
                CP_ASYNC16(bdst + poff + i * 16, bp + i * 8);
            }
            CP_COMMIT();
        }

        // ---- compute on this stage: 4 k16-steps, ldmatrix loads ----
        #pragma unroll
        for (int k16 = 0; k16 < 4; k16++) {
            const uint32_t kb = soff + (uint32_t)(k16 * 32);
            uint32_t a[4][4];
            #pragma unroll
            for (int mi = 0; mi < 4; mi++)
                LDSM_X4(a[mi][0], a[mi][1], a[mi][2], a[mi][3], aoff[mi] + kb);
            uint32_t b4[2][4];
            #pragma unroll
            for (int p = 0; p < 2; p++)
                LDSM_X4(b4[p][0], b4[p][1], b4[p][2], b4[p][3], boff[p] + kb);

            #pragma unroll
            for (int mi = 0; mi < 4; mi++) {
                mma16816(acc[mi][0], a[mi], b4[0][0], b4[0][1]);
                mma16816(acc[mi][1], a[mi], b4[0][2], b4[0][3]);
                mma16816(acc[mi][2], a[mi], b4[1][0], b4[1][1]);
                mma16816(acc[mi][3], a[mi], b4[1][2], b4[1][3]);
            }
        }
        __syncthreads();          // readers done before stage refilled
    }

    // ---- zero reduction buffers ----
    for (int i = tid; i < 3 * 128; i += 256) sRed[i] = 0.f;
    __syncthreads();

    // ---- epilogue: mask/boost/exp, quad-reduce, shared atomics ----
    #pragma unroll
    for (int mi = 0; mi < 4; mi++) {
        const int rl0 = warpM * 64 + mi * 16 + g;
        const int rl1 = rl0 + 8;
        const int r0 = m0 + rl0, r1 = m0 + rl1;
        const float th0 = g_thresh[r0], th1 = g_thresh[r1];
        const int  lab0 = g_label[r0],  lab1 = g_label[r1];

        float s0 = 0.f, bo0 = 0.f, cn0 = 0.f;
        float s1 = 0.f, bo1 = 0.f, cn1 = 0.f;

        #pragma unroll
        for (int ni = 0; ni < 4; ni++) {
            #pragma unroll
            for (int e = 0; e < 2; e++) {
                const int cl = warpN * 32 + ni * 8 + t4 * 2 + e;
                const int c  = n0 + cl;
                if (c < CLS) {
                    if (c != lab0) {
                        float cv = acc[mi][ni][e];
                        cv = fminf(fmaxf(cv, -1.0f), 1.0f);
                        bool hard = (cv > th0);
                        float v = hard ? fmaf(T_BOOST, cv, ALPHA_B) : cv;
                        s0 += __expf(S_SCALE * v);
                        if (hard) { bo0 += v; cn0 += 1.0f; }
                    }
                    if (c != lab1) {
                        float cv = acc[mi][ni][2 + e];
                        cv = fminf(fmaxf(cv, -1.0f), 1.0f);
                        bool hard = (cv > th1);
                        float v = hard ? fmaf(T_BOOST, cv, ALPHA_B) : cv;
                        s1 += __expf(S_SCALE * v);
                        if (hard) { bo1 += v; cn1 += 1.0f; }
                    }
                }
            }
        }

        #pragma unroll
        for (int off = 1; off <= 2; off <<= 1) {
            s0  += __shfl_down_sync(0xffffffffu, s0,  off, 4);
            bo0 += __shfl_down_sync(0xffffffffu, bo0, off, 4);
            cn0 += __shfl_down_sync(0xffffffffu, cn0, off, 4);
            s1  += __shfl_down_sync(0xffffffffu, s1,  off, 4);
            bo1 += __shfl_down_sync(0xffffffffu, bo1, off, 4);
            cn1 += __shfl_down_sync(0xffffffffu, cn1, off, 4);
        }
        if (t4 == 0) {
            atomicAdd(&sRed[rl0],       s0);
            atomicAdd(&sRed[128 + rl0], bo0);
            atomicAdd(&sRed[256 + rl0], cn0);
            atomicAdd(&sRed[rl1],       s1);
            atomicAdd(&sRed[128 + rl1], bo1);
            atomicAdd(&sRed[256 + rl1], cn1);
        }
    }
    __syncthreads();

    if (tid < 128) {
        const int gm = m0 + tid;
        atomicAdd(&g_sumexp[gm],   sRed[tid]);
        atomicAdd(&g_sumboost[gm], sRed[128 + tid]);
        atomicAdd(&g_cnt[gm],      sRed[256 + tid]);
    }
}

// ---------------------------------------------------------------------------
// Kernel C: finalize
// ---------------------------------------------------------------------------
__global__ __launch_bounds__(512) void finalize_kernel(float* __restrict__ out)
{
    const int b = threadIdx.x;
    __shared__ double red[BATCH];

    float gt  = g_gt[b];
    float cnt = g_cnt[b];
    float sb  = g_sumboost[b];

    float lam = sb / fmaxf(cnt, 1.0f);
    float mi  = M0_C + ((cnt > 0.f) ? lam * M1_C : 0.f);
    float cosm = cosf(acosf(gt) + mi);
    float fg = (gt > 0.f) ? cosm : gt;

    double total = (double)g_sumexp[b] + exp((double)(S_SCALE * fg));
    double logp = log(total) - (double)(S_SCALE * fg);
    red[b] = logp;
    __syncthreads();

    #pragma unroll
    for (int s = 256; s > 0; s >>= 1) {
        if (b < s) red[b] += red[b + s];
        __syncthreads();
    }
    if (b == 0) {
        double L = red[0] / (double)BATCH;
        double p = exp(-L);
        double omp = 1.0 - p;
        out[0] = (float)(omp * omp * L);
    }
}

// ---------------------------------------------------------------------------
// Launch
// ---------------------------------------------------------------------------
extern "C" void kernel_launch(void* const* d_in, const int* in_sizes, int n_in,
                              void* d_out, int out_size)
{
    const float* x = nullptr; const void* label = nullptr; const float* W = nullptr;
    for (int i = 0; i < n_in; i++) {
        if (in_sizes[i] == BATCH * FDIM)      x = (const float*)d_in[i];
        else if (in_sizes[i] == BATCH)        label = d_in[i];
        else                                  W = (const float*)d_in[i];
    }
    float* out = (float*)d_out;
    (void)out_size;

    cudaFuncSetAttribute(gemm_mma_kernel,
                         cudaFuncAttributeMaxDynamicSharedMemorySize, SM_TOTAL);

    detect_kernel<<<1, 32>>>((const int*)label);
    wn_kernel<<<(CLS + 7) / 8, 256>>>(W);
    prep_kernel<<<BATCH, 256>>>(x, label, W);

    dim3 grid(BATCH / 128, NTILES);   // (4, 782)
    gemm_mma_kernel<<<grid, 256, SM_TOTAL>>>();

    finalize_kernel<<<1, BATCH>>>(out);
}